// round 2
// baseline (speedup 1.0000x reference)
#include <cuda_runtime.h>
#include <math.h>

#define P        256
#define NT       480
#define NBLK     1000
#define NWIN     976
#define TRI      32896        // P*(P+1)/2
#define SIG_CHUNK  61
#define SIG_NCHUNK 16
#define LPS      260          // padded Lp row stride (floats)
#define CHOL_SMEM ((TRI + 16*LPS + 256 + 256 + 64) * 4)

__device__ float g_wc[64];
__device__ float g_H[(size_t)NBLK * TRI];
__device__ float g_Sigma[(size_t)NWIN * TRI];
__device__ float g_V[NBLK * P];
__device__ float g_mean[NWIN * P];
__device__ float g_res[2 * NWIN];

__device__ __forceinline__ int offj(int j) { return j * P - ((j * (j - 1)) >> 1); }

// ---------------- K0: weights & constants ---------------------------------
__global__ void k_setup(const float* __restrict__ a_in) {
    double a = (double)a_in[0];
    double s1 = 0.0, ap = 1.0;
    for (int u = 0; u < NT; u++) { s1 += ap; ap *= a; }
    double c = (double)NT / s1;
    double s2 = 0.0, a2 = a * a; ap = 1.0;
    for (int u = 0; u < NT; u++) { s2 += ap; ap *= a2; }
    s2 *= c * c;                                   // sum w^2
    double denom = (double)NT - s2 / (double)NT;   // nt*(1 - sum(w^2)/nt^2)
    for (int k = 0; k < 24; k++) g_wc[k]      = (float)pow(a, 20.0 * (23 - k));
    for (int u = 0; u < 20; u++) g_wc[24 + u] = (float)pow(a, (double)(19 - u));
    g_wc[44] = (float)c;
    g_wc[45] = (float)(1.0 / denom);
    g_wc[46] = (float)pow(a, 20.0);
    g_wc[47] = (float)pow(a, 460.0);
    g_wc[48] = (float)(c / (double)NT);
}

// ---------------- K1: block Grams (packed lower) ---------------------------
__global__ void __launch_bounds__(256) k_gram(const float* __restrict__ Y) {
    const int lt = blockIdx.x % 10;
    const int b  = blockIdx.x / 10;
    int ti = 0;
    while (((ti + 1) * (ti + 2)) / 2 <= lt) ti++;
    const int tj = lt - (ti * (ti + 1)) / 2;

    __shared__ __align__(16) float As[20][64];
    __shared__ __align__(16) float Bs[20][64];
    __shared__ float Cs[64][65];
    const int tid = threadIdx.x;
    for (int idx = tid; idx < 20 * 64; idx += 256) {
        int u = idx >> 6, cc = idx & 63;
        size_t row = (size_t)(b * 20 + u) * P;
        As[u][cc] = g_wc[24 + u] * Y[row + ti * 64 + cc];
        Bs[u][cc] = Y[row + tj * 64 + cc];
    }
    __syncthreads();

    const int tx = tid & 15, ty = tid >> 4;
    float acc[4][4];
#pragma unroll
    for (int r = 0; r < 4; r++)
#pragma unroll
        for (int c = 0; c < 4; c++) acc[r][c] = 0.f;

#pragma unroll
    for (int u = 0; u < 20; u++) {
        float4 av = *(const float4*)&As[u][ty * 4];
        float4 bv = *(const float4*)&Bs[u][tx * 4];
        float ar[4] = {av.x, av.y, av.z, av.w};
        float br[4] = {bv.x, bv.y, bv.z, bv.w};
#pragma unroll
        for (int r = 0; r < 4; r++)
#pragma unroll
            for (int c = 0; c < 4; c++) acc[r][c] += ar[r] * br[c];
    }
#pragma unroll
    for (int r = 0; r < 4; r++)
#pragma unroll
        for (int c = 0; c < 4; c++) Cs[ty * 4 + r][tx * 4 + c] = acc[r][c];
    __syncthreads();

    // cooperative packed write: column segments are contiguous
    float* Hb = g_H + (size_t)b * TRI;
    for (int idx = tid; idx < 64 * 64; idx += 256) {
        int cc = idx >> 6, rr = idx & 63;         // cc = local col, rr = local row
        if (ti == tj && rr < cc) continue;
        int j = tj * 64 + cc, i = ti * 64 + rr;
        Hb[offj(j) + i - j] = Cs[rr][cc];
    }
}

// ---------------- K2: weighted block row-sums ------------------------------
__global__ void k_vsum(const float* __restrict__ Y) {
    const int b = blockIdx.x, i = threadIdx.x;
    float s = 0.f;
#pragma unroll
    for (int u = 0; u < 20; u++)
        s += g_wc[24 + u] * Y[(size_t)(b * 20 + u) * P + i];
    g_V[b * P + i] = s;
}

// ---------------- K3: per-window means --------------------------------------
__global__ void k_mean() {
    const int w = blockIdx.x, i = threadIdx.x;
    float s = 0.f;
#pragma unroll
    for (int k = 0; k < 24; k++)
        s += g_wc[k] * g_V[(w + k) * P + i];
    g_mean[w * P + i] = s * g_wc[48];
}

// ---------------- K4: Sigma via sliding recurrence --------------------------
__global__ void k_sigma() {
    int e = blockIdx.x * 256 + threadIdx.x;
    if (e >= TRI) return;
    int c = blockIdx.y;
    int j = (int)((513.0 - sqrt(513.0 * 513.0 - 8.0 * (double)e)) * 0.5);
    if (j < 0) j = 0; if (j > 255) j = 255;
    while (j < 255 && offj(j + 1) <= e) j++;
    while (j > 0 && offj(j) > e) j--;
    int i = e - offj(j) + j;

    const float a20 = g_wc[46], gg0 = g_wc[47], cw = g_wc[44], inv = g_wc[45];
    const int w0 = c * SIG_CHUNK;
    float T = 0.f;
    for (int k = 0; k < 24; k++) T += g_wc[k] * g_H[(size_t)(w0 + k) * TRI + e];
    for (int s = 0; s < SIG_CHUNK; s++) {
        int w = w0 + s;
        float m = g_mean[w * P + i] * g_mean[w * P + j];
        g_Sigma[(size_t)w * TRI + e] = (cw * T - 480.0f * m) * inv;
        if (s + 1 < SIG_CHUNK)
            T = a20 * (T - gg0 * g_H[(size_t)w * TRI + e]) + g_H[(size_t)(w + 24) * TRI + e];
    }
}

// ---------------- K5: batched packed Cholesky + solves + epilogue -----------
__global__ void __launch_bounds__(512, 1) k_chol(const float* __restrict__ Y) {
    extern __shared__ float sm[];
    float* A   = sm;                    // TRI packed col-major lower
    float* Lp  = sm + TRI;              // 16 x LPS, k-major panel
    float* yv  = Lp + 16 * LPS;         // 256
    float* zv  = yv + 256;              // 256
    float* red = zv + 256;              // 64
    const int w = blockIdx.x;
    const int tid = threadIdx.x;

    { // load Sigma (float4)
        const float4* src = (const float4*)(g_Sigma + (size_t)w * TRI);
        float4* dst = (float4*)A;
        for (int idx = tid; idx < TRI / 4; idx += 512) dst[idx] = src[idx];
    }
    __syncthreads();

    for (int kb = 0; kb < 16; kb++) {
        const int j0 = kb * 16;
        // ---- panel factorization (cols j0..j0+15, full height) ----
        for (int jj = 0; jj < 16; jj++) {
            const int j = j0 + jj;
            float* colj = A + offj(j);
            if (tid == 0) red[0] = rsqrtf(colj[0]);
            __syncthreads();
            const float rinv = red[0];
            const int h = P - j;
            for (int r = tid; r < h; r += 512) colj[r] *= rinv;
            __syncthreads();
            for (int c = jj + 1; c < 16; c++) {
                const int jc = j0 + c;
                const float Ljc = colj[jc - j];
                float* colc = A + offj(jc);
                const int h2 = P - jc;
                for (int r = tid; r < h2; r += 512) colc[r] -= colj[r + (jc - j)] * Ljc;
            }
            __syncthreads();
        }
        // ---- trailing SYRK ----
        const int h = P - (j0 + 16);
        if (h > 0) {
            for (int idx = tid; idx < 16 * h; idx += 512) {
                int k = idx / h, r = idx - k * h;
                int i = j0 + 16 + r;
                Lp[k * LPS + i] = A[offj(j0 + k) + i - (j0 + k)];
            }
            __syncthreads();
            const int nb = h >> 2;
            const int ntiles = nb * (nb + 1) / 2;
            for (int t = tid; t < ntiles; t += 512) {
                int bi = (int)((sqrtf(8.f * (float)t + 1.f) - 1.f) * 0.5f);
                while ((bi + 1) * (bi + 2) / 2 <= t) bi++;
                while (bi * (bi + 1) / 2 > t) bi--;
                const int bj = t - bi * (bi + 1) / 2;
                const int i0 = j0 + 16 + 4 * bi, jj0 = j0 + 16 + 4 * bj;
                float acc[4][4];
#pragma unroll
                for (int r = 0; r < 4; r++)
#pragma unroll
                    for (int c = 0; c < 4; c++) acc[r][c] = 0.f;
#pragma unroll
                for (int k = 0; k < 16; k++) {
                    float4 aa = *(const float4*)&Lp[k * LPS + i0];
                    float4 bb = *(const float4*)&Lp[k * LPS + jj0];
                    float ar[4] = {aa.x, aa.y, aa.z, aa.w};
                    float br[4] = {bb.x, bb.y, bb.z, bb.w};
#pragma unroll
                    for (int r = 0; r < 4; r++)
#pragma unroll
                        for (int c = 0; c < 4; c++) acc[r][c] += ar[r] * br[c];
                }
#pragma unroll
                for (int c = 0; c < 4; c++) {
                    const int j = jj0 + c;
                    float* colc = A + offj(j);
#pragma unroll
                    for (int r = 0; r < 4; r++) {
                        const int i = i0 + r;
                        if (i >= j) colc[i - j] -= acc[r][c];
                    }
                }
            }
            __syncthreads();
        }
    }

    // ---- forward: L y = 1 ----
    for (int r = tid; r < P; r += 512) yv[r] = 1.0f;
    __syncthreads();
    for (int jb = 0; jb < 16; jb++) {
        if (tid < 32) {
            for (int jj = 0; jj < 16; jj++) {
                const int j = jb * 16 + jj;
                const float* colj = A + offj(j);
                if (tid == 0) yv[j] = yv[j] / colj[0];
                __syncwarp();
                const float yj = yv[j];
                const int rem = 15 - jj;
                if (tid >= 1 && tid <= rem) yv[j + tid] -= colj[tid] * yj;
                __syncwarp();
            }
        }
        __syncthreads();
        const int base = (jb + 1) * 16;
        for (int r = base + tid; r < P; r += 512) {
            float s = 0.f;
#pragma unroll
            for (int jj = 0; jj < 16; jj++) {
                const int j = jb * 16 + jj;
                s += A[offj(j) + r - j] * yv[j];
            }
            yv[r] -= s;
        }
        __syncthreads();
    }

    // ---- backward: L^T z = y ----
    for (int r = tid; r < P; r += 512) zv[r] = yv[r];
    __syncthreads();
    for (int jb = 15; jb >= 0; jb--) {
        if (tid < 32) {
            for (int jj = 15; jj >= 0; jj--) {
                const int j = jb * 16 + jj;
                const float* colj = A + offj(j);
                const int rem = 15 - jj;
                float s = 0.f;
                if (tid >= 1 && tid <= rem) s = colj[tid] * zv[j + tid];
#pragma unroll
                for (int o = 16; o > 0; o >>= 1) s += __shfl_down_sync(0xffffffffu, s, o);
                if (tid == 0) zv[j] = (zv[j] - s) / colj[0];
                __syncwarp();
            }
        }
        __syncthreads();
        for (int i = tid; i < jb * 16; i += 512) {
            const float* coli = A + offj(i);
            float s = 0.f;
#pragma unroll
            for (int kk = 0; kk < 16; kk++) {
                const int k = jb * 16 + kk;
                s += coli[k - i] * zv[k];
            }
            zv[i] -= s;
        }
        __syncthreads();
    }

    // ---- normalize: w_opt = 256 * z / sum(z) ----
    float s = (tid < P) ? zv[tid] : 0.f;
#pragma unroll
    for (int o = 16; o > 0; o >>= 1) s += __shfl_down_sync(0xffffffffu, s, o);
    if ((tid & 31) == 0) red[tid >> 5] = s;
    __syncthreads();
    if (tid == 0) {
        float tot = 0.f;
        for (int k = 0; k < 16; k++) tot += red[k];
        red[32] = 256.0f / tot;
    }
    __syncthreads();
    const float scale = red[32];

    // ---- epilogue: realized test-window returns ----
    float se = 0.f, sq = 0.f;
    for (int t = 0; t < 20; t++) {
        const float* yr = Y + (size_t)((w + 24) * 20 + t) * P;
        float part = (tid < P) ? yr[tid] * zv[tid] : 0.f;
#pragma unroll
        for (int o = 16; o > 0; o >>= 1) part += __shfl_down_sync(0xffffffffu, part, o);
        if ((tid & 31) == 0) red[tid >> 5] = part;
        __syncthreads();
        if (tid == 0) {
            float rt = 0.f;
            for (int k = 0; k < 16; k++) rt += red[k];
            rt *= scale;
            se += rt; sq += rt * rt;
        }
        __syncthreads();
    }
    if (tid == 0) {
        g_res[w] = se;
        g_res[NWIN + w] = (sq - se * se / 20.f) / 19.f;
    }
}

// ---------------- K6: final reduction ---------------------------------------
__global__ void k_final(float* out) {
    __shared__ float rb[64];
    const int tid = threadIdx.x;
    float se = 0.f, ss = 0.f;
    for (int w = tid; w < NWIN; w += 256) { se += g_res[w]; ss += g_res[NWIN + w]; }
#pragma unroll
    for (int o = 16; o > 0; o >>= 1) {
        se += __shfl_down_sync(0xffffffffu, se, o);
        ss += __shfl_down_sync(0xffffffffu, ss, o);
    }
    if ((tid & 31) == 0) { rb[tid >> 5] = se; rb[32 + (tid >> 5)] = ss; }
    __syncthreads();
    if (tid == 0) {
        float te = 0.f, ts = 0.f;
        for (int k = 0; k < 8; k++) { te += rb[k]; ts += rb[32 + k]; }
        float mu  = te / (float)NWIN / 20.f * 252.f;
        float vol = sqrtf(ts / (float)NWIN * 252.f);
        out[0] = vol;
        out[1] = mu;
        out[2] = mu / vol;
    }
}

extern "C" void kernel_launch(void* const* d_in, const int* in_sizes, int n_in,
                              void* d_out, int out_size) {
    const float* Y = (const float*)d_in[0];
    const float* a = (const float*)d_in[1];
    cudaFuncSetAttribute(k_chol, cudaFuncAttributeMaxDynamicSharedMemorySize, CHOL_SMEM);
    k_setup<<<1, 1>>>(a);
    k_gram<<<NBLK * 10, 256>>>(Y);
    k_vsum<<<NBLK, 256>>>(Y);
    k_mean<<<NWIN, 256>>>();
    dim3 gs((TRI + 255) / 256, SIG_NCHUNK);
    k_sigma<<<gs, 256>>>();
    k_chol<<<NWIN, 512, CHOL_SMEM>>>(Y);
    k_final<<<1, 256>>>((float*)d_out);
}

// round 3
// speedup vs baseline: 1.1329x; 1.1329x over previous
#include <cuda_runtime.h>
#include <math.h>

#define P        256
#define NT       480
#define NBLK     1000
#define NWIN     976
#define TRI      32896        // P*(P+1)/2
#define SIG_CHUNK  61
#define SIG_NCHUNK 16
#define LPS      260          // padded Lp row stride (floats)
#define CHOL_SMEM ((TRI + 16*LPS + 256 + 256 + 64) * 4)

__device__ float g_wc[64];
__device__ float g_H[(size_t)NBLK * TRI];
__device__ float g_Sigma[(size_t)NWIN * TRI];
__device__ float g_V[NBLK * P];
__device__ float g_mean[NWIN * P];
__device__ float g_res[2 * NWIN];

__device__ __forceinline__ int offj(int j) { return j * P - ((j * (j - 1)) >> 1); }

// ---------------- K0: weights & constants ---------------------------------
__global__ void k_setup(const float* __restrict__ a_in) {
    double a = (double)a_in[0];
    double s1 = 0.0, ap = 1.0;
    for (int u = 0; u < NT; u++) { s1 += ap; ap *= a; }
    double c = (double)NT / s1;
    double s2 = 0.0, a2 = a * a; ap = 1.0;
    for (int u = 0; u < NT; u++) { s2 += ap; ap *= a2; }
    s2 *= c * c;
    double denom = (double)NT - s2 / (double)NT;
    for (int k = 0; k < 24; k++) g_wc[k]      = (float)pow(a, 20.0 * (23 - k));
    for (int u = 0; u < 20; u++) g_wc[24 + u] = (float)pow(a, (double)(19 - u));
    g_wc[44] = (float)c;
    g_wc[45] = (float)(1.0 / denom);
    g_wc[46] = (float)pow(a, 20.0);
    g_wc[47] = (float)pow(a, 460.0);
    g_wc[48] = (float)(c / (double)NT);
}

// ---------------- K1: block Grams (packed lower) ---------------------------
__global__ void __launch_bounds__(256) k_gram(const float* __restrict__ Y) {
    const int lt = blockIdx.x % 10;
    const int b  = blockIdx.x / 10;
    int ti = 0;
    while (((ti + 1) * (ti + 2)) / 2 <= lt) ti++;
    const int tj = lt - (ti * (ti + 1)) / 2;

    __shared__ __align__(16) float As[20][64];
    __shared__ __align__(16) float Bs[20][64];
    __shared__ float Cs[64][65];
    const int tid = threadIdx.x;
    for (int idx = tid; idx < 20 * 64; idx += 256) {
        int u = idx >> 6, cc = idx & 63;
        size_t row = (size_t)(b * 20 + u) * P;
        As[u][cc] = g_wc[24 + u] * Y[row + ti * 64 + cc];
        Bs[u][cc] = Y[row + tj * 64 + cc];
    }
    __syncthreads();

    const int tx = tid & 15, ty = tid >> 4;
    float acc[4][4];
#pragma unroll
    for (int r = 0; r < 4; r++)
#pragma unroll
        for (int c = 0; c < 4; c++) acc[r][c] = 0.f;

#pragma unroll
    for (int u = 0; u < 20; u++) {
        float4 av = *(const float4*)&As[u][ty * 4];
        float4 bv = *(const float4*)&Bs[u][tx * 4];
        float ar[4] = {av.x, av.y, av.z, av.w};
        float br[4] = {bv.x, bv.y, bv.z, bv.w};
#pragma unroll
        for (int r = 0; r < 4; r++)
#pragma unroll
            for (int c = 0; c < 4; c++) acc[r][c] += ar[r] * br[c];
    }
#pragma unroll
    for (int r = 0; r < 4; r++)
#pragma unroll
        for (int c = 0; c < 4; c++) Cs[ty * 4 + r][tx * 4 + c] = acc[r][c];
    __syncthreads();

    float* Hb = g_H + (size_t)b * TRI;
    for (int idx = tid; idx < 64 * 64; idx += 256) {
        int cc = idx >> 6, rr = idx & 63;
        if (ti == tj && rr < cc) continue;
        int j = tj * 64 + cc, i = ti * 64 + rr;
        Hb[offj(j) + i - j] = Cs[rr][cc];
    }
}

// ---------------- K2: weighted block row-sums ------------------------------
__global__ void k_vsum(const float* __restrict__ Y) {
    const int b = blockIdx.x, i = threadIdx.x;
    float s = 0.f;
#pragma unroll
    for (int u = 0; u < 20; u++)
        s += g_wc[24 + u] * Y[(size_t)(b * 20 + u) * P + i];
    g_V[b * P + i] = s;
}

// ---------------- K3: per-window means --------------------------------------
__global__ void k_mean() {
    const int w = blockIdx.x, i = threadIdx.x;
    float s = 0.f;
#pragma unroll
    for (int k = 0; k < 24; k++)
        s += g_wc[k] * g_V[(w + k) * P + i];
    g_mean[w * P + i] = s * g_wc[48];
}

// ---------------- K4: Sigma via sliding recurrence --------------------------
__global__ void k_sigma() {
    int e = blockIdx.x * 256 + threadIdx.x;
    if (e >= TRI) return;
    int c = blockIdx.y;
    int j = (int)((513.0 - sqrt(513.0 * 513.0 - 8.0 * (double)e)) * 0.5);
    if (j < 0) j = 0; if (j > 255) j = 255;
    while (j < 255 && offj(j + 1) <= e) j++;
    while (j > 0 && offj(j) > e) j--;
    int i = e - offj(j) + j;

    const float a20 = g_wc[46], gg0 = g_wc[47], cw = g_wc[44], inv = g_wc[45];
    const int w0 = c * SIG_CHUNK;
    float T = 0.f;
    for (int k = 0; k < 24; k++) T += g_wc[k] * g_H[(size_t)(w0 + k) * TRI + e];
    for (int s = 0; s < SIG_CHUNK; s++) {
        int w = w0 + s;
        float m = g_mean[w * P + i] * g_mean[w * P + j];
        g_Sigma[(size_t)w * TRI + e] = (cw * T - 480.0f * m) * inv;
        if (s + 1 < SIG_CHUNK)
            T = a20 * (T - gg0 * g_H[(size_t)w * TRI + e]) + g_H[(size_t)(w + 24) * TRI + e];
    }
}

// ---------------- K5: batched packed Cholesky + solves + epilogue -----------
// Right-looking blocked (NB=16): warp0 factors diag block (syncwarp only)
// while warps 1..15 stage the sub-panel k-major; row-parallel TRSM; 8x8 SYRK.
__global__ void __launch_bounds__(512, 1) k_chol(const float* __restrict__ Y) {
    extern __shared__ float sm[];
    float* A   = sm;                    // TRI packed col-major lower
    float* Lp  = sm + TRI;              // 16 x LPS, k-major panel
    float* yv  = Lp + 16 * LPS;         // 256
    float* zv  = yv + 256;              // 256
    float* red = zv + 256;              // 64 (red[0..15] = rdiag of panel)
    const int w = blockIdx.x;
    const int tid = threadIdx.x;

    { // load Sigma (float4)
        const float4* src = (const float4*)(g_Sigma + (size_t)w * TRI);
        float4* dst = (float4*)A;
        for (int idx = tid; idx < TRI / 4; idx += 512) dst[idx] = src[idx];
    }
    __syncthreads();

    for (int kb = 0; kb < 16; kb++) {
        const int j0 = kb * 16;
        const int h  = P - (j0 + 16);        // rows below the diag block

        // ---- warp 0: factor 16x16 diag block; warps 1..15: stage panel ----
        if (tid < 32) {
            const int r = tid;               // lane = row within block
#pragma unroll 1
            for (int jj = 0; jj < 16; jj++) {
                float* colj = A + offj(j0 + jj);
                if (r == 0) red[jj] = rsqrtf(colj[0]);
                __syncwarp();
                const float rinv = red[jj];
                if (r >= jj && r < 16) colj[r - jj] *= rinv;
                __syncwarp();
                if (r > jj && r < 16) {
                    const float lr = colj[r - jj];
                    for (int c = jj + 1; c <= r; c++) {
                        A[offj(j0 + c) + r - c] -= lr * colj[c - jj];
                    }
                }
                __syncwarp();
            }
        } else if (h > 0) {
            for (int idx = tid - 32; idx < 16 * h; idx += 480) {
                int k = idx / h, rr = idx - k * h;
                int i = j0 + 16 + rr;
                Lp[k * LPS + i] = A[offj(j0 + k) + i - (j0 + k)];
            }
        }
        __syncthreads();
        if (h == 0) continue;

        // ---- row-parallel TRSM: each thread solves one row of L21 ----
        if (tid < h) {
            const int i = j0 + 16 + tid;
            float y[16];
#pragma unroll
            for (int k = 0; k < 16; k++) y[k] = Lp[k * LPS + i];
#pragma unroll
            for (int k = 0; k < 16; k++) {
                float v = y[k];
                const float* colk = A + offj(j0 + k);
#pragma unroll
                for (int m = 0; m < 16; m++) {
                    if (m < k) { /* handled below */ }
                }
                // v already accumulated below; compute serially:
                y[k] = v * red[k];
                const float yk = y[k];
#pragma unroll
                for (int m2 = 1; m2 < 16; m2++) {
                    if (k + m2 < 16) y[k + m2] -= colk[m2] * yk;
                }
            }
#pragma unroll
            for (int k = 0; k < 16; k++) {
                Lp[k * LPS + i] = y[k];
                A[offj(j0 + k) + i - (j0 + k)] = y[k];
            }
        }
        __syncthreads();

        // ---- trailing SYRK: A22 -= L21 L21^T, 8x8 register tiles ----
        const int nb = h >> 3;
        const int ntiles = nb * (nb + 1) / 2;
        for (int t = tid; t < ntiles; t += 512) {
            int bi = (int)((sqrtf(8.f * (float)t + 1.f) - 1.f) * 0.5f);
            while ((bi + 1) * (bi + 2) / 2 <= t) bi++;
            while (bi * (bi + 1) / 2 > t) bi--;
            const int bj = t - bi * (bi + 1) / 2;
            const int i0 = j0 + 16 + 8 * bi, jj0 = j0 + 16 + 8 * bj;
            float acc[8][8];
#pragma unroll
            for (int r = 0; r < 8; r++)
#pragma unroll
                for (int c = 0; c < 8; c++) acc[r][c] = 0.f;
#pragma unroll
            for (int k = 0; k < 16; k++) {
                const float* lk = Lp + k * LPS;
                float4 a0 = *(const float4*)&lk[i0];
                float4 a1 = *(const float4*)&lk[i0 + 4];
                float4 b0 = *(const float4*)&lk[jj0];
                float4 b1 = *(const float4*)&lk[jj0 + 4];
                float ar[8] = {a0.x, a0.y, a0.z, a0.w, a1.x, a1.y, a1.z, a1.w};
                float br[8] = {b0.x, b0.y, b0.z, b0.w, b1.x, b1.y, b1.z, b1.w};
#pragma unroll
                for (int r = 0; r < 8; r++)
#pragma unroll
                    for (int c = 0; c < 8; c++) acc[r][c] += ar[r] * br[c];
            }
#pragma unroll
            for (int c = 0; c < 8; c++) {
                const int j = jj0 + c;
                float* colc = A + offj(j);
#pragma unroll
                for (int r = 0; r < 8; r++) {
                    const int i = i0 + r;
                    if (i >= j) colc[i - j] -= acc[r][c];
                }
            }
        }
        __syncthreads();
    }

    // ---- forward: L y = 1 ----
    for (int r = tid; r < P; r += 512) yv[r] = 1.0f;
    __syncthreads();
    for (int jb = 0; jb < 16; jb++) {
        if (tid < 32) {
            for (int jj = 0; jj < 16; jj++) {
                const int j = jb * 16 + jj;
                const float* colj = A + offj(j);
                if (tid == 0) yv[j] = yv[j] / colj[0];
                __syncwarp();
                const float yj = yv[j];
                const int rem = 15 - jj;
                if (tid >= 1 && tid <= rem) yv[j + tid] -= colj[tid] * yj;
                __syncwarp();
            }
        }
        __syncthreads();
        const int base = (jb + 1) * 16;
        for (int r = base + tid; r < P; r += 512) {
            float s = 0.f;
#pragma unroll
            for (int jj = 0; jj < 16; jj++) {
                const int j = jb * 16 + jj;
                s += A[offj(j) + r - j] * yv[j];
            }
            yv[r] -= s;
        }
        __syncthreads();
    }

    // ---- backward: L^T z = y ----
    for (int r = tid; r < P; r += 512) zv[r] = yv[r];
    __syncthreads();
    for (int jb = 15; jb >= 0; jb--) {
        if (tid < 32) {
            for (int jj = 15; jj >= 0; jj--) {
                const int j = jb * 16 + jj;
                const float* colj = A + offj(j);
                const int rem = 15 - jj;
                float s = 0.f;
                if (tid >= 1 && tid <= rem) s = colj[tid] * zv[j + tid];
#pragma unroll
                for (int o = 16; o > 0; o >>= 1) s += __shfl_down_sync(0xffffffffu, s, o);
                if (tid == 0) zv[j] = (zv[j] - s) / colj[0];
                __syncwarp();
            }
        }
        __syncthreads();
        for (int i = tid; i < jb * 16; i += 512) {
            const float* coli = A + offj(i);
            float s = 0.f;
#pragma unroll
            for (int kk = 0; kk < 16; kk++) {
                const int k = jb * 16 + kk;
                s += coli[k - i] * zv[k];
            }
            zv[i] -= s;
        }
        __syncthreads();
    }

    // ---- normalize: w_opt = 256 * z / sum(z) ----
    float s = (tid < P) ? zv[tid] : 0.f;
#pragma unroll
    for (int o = 16; o > 0; o >>= 1) s += __shfl_down_sync(0xffffffffu, s, o);
    if ((tid & 31) == 0) red[tid >> 5] = s;
    __syncthreads();
    if (tid == 0) {
        float tot = 0.f;
        for (int k = 0; k < 16; k++) tot += red[k];
        red[32] = 256.0f / tot;
    }
    __syncthreads();
    const float scale = red[32];

    // ---- epilogue: realized test-window returns ----
    float se = 0.f, sq = 0.f;
    for (int t = 0; t < 20; t++) {
        const float* yr = Y + (size_t)((w + 24) * 20 + t) * P;
        float part = (tid < P) ? yr[tid] * zv[tid] : 0.f;
#pragma unroll
        for (int o = 16; o > 0; o >>= 1) part += __shfl_down_sync(0xffffffffu, part, o);
        if ((tid & 31) == 0) red[tid >> 5] = part;
        __syncthreads();
        if (tid == 0) {
            float rt = 0.f;
            for (int k = 0; k < 16; k++) rt += red[k];
            rt *= scale;
            se += rt; sq += rt * rt;
        }
        __syncthreads();
    }
    if (tid == 0) {
        g_res[w] = se;
        g_res[NWIN + w] = (sq - se * se / 20.f) / 19.f;
    }
}

// ---------------- K6: final reduction ---------------------------------------
__global__ void k_final(float* out) {
    __shared__ float rb[64];
    const int tid = threadIdx.x;
    float se = 0.f, ss = 0.f;
    for (int w = tid; w < NWIN; w += 256) { se += g_res[w]; ss += g_res[NWIN + w]; }
#pragma unroll
    for (int o = 16; o > 0; o >>= 1) {
        se += __shfl_down_sync(0xffffffffu, se, o);
        ss += __shfl_down_sync(0xffffffffu, ss, o);
    }
    if ((tid & 31) == 0) { rb[tid >> 5] = se; rb[32 + (tid >> 5)] = ss; }
    __syncthreads();
    if (tid == 0) {
        float te = 0.f, ts = 0.f;
        for (int k = 0; k < 8; k++) { te += rb[k]; ts += rb[32 + k]; }
        float mu  = te / (float)NWIN / 20.f * 252.f;
        float vol = sqrtf(ts / (float)NWIN * 252.f);
        out[0] = vol;
        out[1] = mu;
        out[2] = mu / vol;
    }
}

extern "C" void kernel_launch(void* const* d_in, const int* in_sizes, int n_in,
                              void* d_out, int out_size) {
    const float* Y = (const float*)d_in[0];
    const float* a = (const float*)d_in[1];
    cudaFuncSetAttribute(k_chol, cudaFuncAttributeMaxDynamicSharedMemorySize, CHOL_SMEM);
    k_setup<<<1, 1>>>(a);
    k_gram<<<NBLK * 10, 256>>>(Y);
    k_vsum<<<NBLK, 256>>>(Y);
    k_mean<<<NWIN, 256>>>();
    dim3 gs((TRI + 255) / 256, SIG_NCHUNK);
    k_sigma<<<gs, 256>>>();
    k_chol<<<NWIN, 512, CHOL_SMEM>>>(Y);
    k_final<<<1, 256>>>((float*)d_out);
}

// round 4
// speedup vs baseline: 1.4786x; 1.3052x over previous
#include <cuda_runtime.h>
#include <math.h>

#define P        256
#define NT       480
#define NBLK     1000
#define NWIN     976
#define TRI      32896        // P*(P+1)/2
#define SIG_CHUNK  61
#define SIG_NCHUNK 16
#define LPS      260          // padded Lp row stride (floats)
#define CHOL_SMEM ((TRI + 16*LPS + 256 + 256 + 256 + 64) * 4)
#define FULLM 0xffffffffu

__device__ float g_wc[64];
__device__ float g_H[(size_t)NBLK * TRI];
__device__ float g_Sigma[(size_t)NWIN * TRI];
__device__ float g_V[NBLK * P];
__device__ float g_mean[NWIN * P];
__device__ float g_res[2 * NWIN];

__device__ __forceinline__ int offj(int j) { return j * P - ((j * (j - 1)) >> 1); }

// ---------------- K0: weights & constants ---------------------------------
__global__ void k_setup(const float* __restrict__ a_in) {
    double a = (double)a_in[0];
    double s1 = 0.0, ap = 1.0;
    for (int u = 0; u < NT; u++) { s1 += ap; ap *= a; }
    double c = (double)NT / s1;
    double s2 = 0.0, a2 = a * a; ap = 1.0;
    for (int u = 0; u < NT; u++) { s2 += ap; ap *= a2; }
    s2 *= c * c;
    double denom = (double)NT - s2 / (double)NT;
    for (int k = 0; k < 24; k++) g_wc[k]      = (float)pow(a, 20.0 * (23 - k));
    for (int u = 0; u < 20; u++) g_wc[24 + u] = (float)pow(a, (double)(19 - u));
    g_wc[44] = (float)c;
    g_wc[45] = (float)(1.0 / denom);
    g_wc[46] = (float)pow(a, 20.0);
    g_wc[47] = (float)pow(a, 460.0);
    g_wc[48] = (float)(c / (double)NT);
}

// ---------------- K1: block Grams (packed lower) ---------------------------
__global__ void __launch_bounds__(256) k_gram(const float* __restrict__ Y) {
    const int lt = blockIdx.x % 10;
    const int b  = blockIdx.x / 10;
    int ti = 0;
    while (((ti + 1) * (ti + 2)) / 2 <= lt) ti++;
    const int tj = lt - (ti * (ti + 1)) / 2;

    __shared__ __align__(16) float As[20][64];
    __shared__ __align__(16) float Bs[20][64];
    __shared__ float Cs[64][65];
    const int tid = threadIdx.x;
    for (int idx = tid; idx < 20 * 64; idx += 256) {
        int u = idx >> 6, cc = idx & 63;
        size_t row = (size_t)(b * 20 + u) * P;
        As[u][cc] = g_wc[24 + u] * Y[row + ti * 64 + cc];
        Bs[u][cc] = Y[row + tj * 64 + cc];
    }
    __syncthreads();

    const int tx = tid & 15, ty = tid >> 4;
    float acc[4][4];
#pragma unroll
    for (int r = 0; r < 4; r++)
#pragma unroll
        for (int c = 0; c < 4; c++) acc[r][c] = 0.f;

#pragma unroll
    for (int u = 0; u < 20; u++) {
        float4 av = *(const float4*)&As[u][ty * 4];
        float4 bv = *(const float4*)&Bs[u][tx * 4];
        float ar[4] = {av.x, av.y, av.z, av.w};
        float br[4] = {bv.x, bv.y, bv.z, bv.w};
#pragma unroll
        for (int r = 0; r < 4; r++)
#pragma unroll
            for (int c = 0; c < 4; c++) acc[r][c] += ar[r] * br[c];
    }
#pragma unroll
    for (int r = 0; r < 4; r++)
#pragma unroll
        for (int c = 0; c < 4; c++) Cs[ty * 4 + r][tx * 4 + c] = acc[r][c];
    __syncthreads();

    float* Hb = g_H + (size_t)b * TRI;
    for (int idx = tid; idx < 64 * 64; idx += 256) {
        int cc = idx >> 6, rr = idx & 63;
        if (ti == tj && rr < cc) continue;
        int j = tj * 64 + cc, i = ti * 64 + rr;
        Hb[offj(j) + i - j] = Cs[rr][cc];
    }
}

// ---------------- K2: weighted block row-sums ------------------------------
__global__ void k_vsum(const float* __restrict__ Y) {
    const int b = blockIdx.x, i = threadIdx.x;
    float s = 0.f;
#pragma unroll
    for (int u = 0; u < 20; u++)
        s += g_wc[24 + u] * Y[(size_t)(b * 20 + u) * P + i];
    g_V[b * P + i] = s;
}

// ---------------- K3: per-window means --------------------------------------
__global__ void k_mean() {
    const int w = blockIdx.x, i = threadIdx.x;
    float s = 0.f;
#pragma unroll
    for (int k = 0; k < 24; k++)
        s += g_wc[k] * g_V[(w + k) * P + i];
    g_mean[w * P + i] = s * g_wc[48];
}

// ---------------- K4: Sigma via sliding recurrence --------------------------
__global__ void k_sigma() {
    int e = blockIdx.x * 256 + threadIdx.x;
    if (e >= TRI) return;
    int c = blockIdx.y;
    int j = (int)((513.0 - sqrt(513.0 * 513.0 - 8.0 * (double)e)) * 0.5);
    if (j < 0) j = 0; if (j > 255) j = 255;
    while (j < 255 && offj(j + 1) <= e) j++;
    while (j > 0 && offj(j) > e) j--;
    int i = e - offj(j) + j;

    const float a20 = g_wc[46], gg0 = g_wc[47], cw = g_wc[44], inv = g_wc[45];
    const int w0 = c * SIG_CHUNK;
    float T = 0.f;
    for (int k = 0; k < 24; k++) T += g_wc[k] * g_H[(size_t)(w0 + k) * TRI + e];
    for (int s = 0; s < SIG_CHUNK; s++) {
        int w = w0 + s;
        float m = g_mean[w * P + i] * g_mean[w * P + j];
        g_Sigma[(size_t)w * TRI + e] = (cw * T - 480.0f * m) * inv;
        if (s + 1 < SIG_CHUNK)
            T = a20 * (T - gg0 * g_H[(size_t)w * TRI + e]) + g_H[(size_t)(w + 24) * TRI + e];
    }
}

// ---------------- K5: batched packed Cholesky + solves + epilogue -----------
__global__ void __launch_bounds__(512, 1) k_chol(const float* __restrict__ Y) {
    extern __shared__ float sm[];
    float* A   = sm;                    // TRI packed col-major lower
    float* Lp  = sm + TRI;              // 16 x LPS, k-major panel
    float* yv  = Lp + 16 * LPS;         // 256
    float* zv  = yv + 256;              // 256
    float* rd  = zv + 256;              // 256: 1/L[j][j]
    float* red = rd + 256;              // 64 scratch
    const int w = blockIdx.x;
    const int tid = threadIdx.x;
    const int lane = tid & 31;

    { // load Sigma (float4)
        const float4* src = (const float4*)(g_Sigma + (size_t)w * TRI);
        float4* dst = (float4*)A;
        for (int idx = tid; idx < TRI / 4; idx += 512) dst[idx] = src[idx];
    }
    __syncthreads();

    for (int kb = 0; kb < 16; kb++) {
        const int j0 = kb * 16;
        const int h  = P - (j0 + 16);

        // ---- warp 0: register Cholesky of 16x16 diag block;
        //      warps 1..15: stage sub-panel k-major ----
        if (tid < 32) {
            const int r = lane;
            float a[16];
#pragma unroll
            for (int c = 0; c < 16; c++)
                a[c] = (r >= c) ? A[offj(j0 + c) + r - c] : 0.f;
#pragma unroll
            for (int jj = 0; jj < 16; jj++) {
                float d = __shfl_sync(FULLM, a[jj], jj);
                float rinv = rsqrtf(d);
                if (r == jj) rd[j0 + jj] = rinv;
                a[jj] *= rinv;                      // valid for r>=jj; garbage rows harmless
#pragma unroll
                for (int c = jj + 1; c < 16; c++) {
                    float Lcjj = __shfl_sync(FULLM, a[jj], c);
                    if (r >= c) a[c] -= a[jj] * Lcjj;
                }
            }
#pragma unroll
            for (int c = 0; c < 16; c++)
                if (r >= c) A[offj(j0 + c) + r - c] = a[c];
        } else if (h > 0) {
            for (int idx = tid - 32; idx < 16 * h; idx += 480) {
                int k = idx / h, rr = idx - k * h;
                int i = j0 + 16 + rr;
                Lp[k * LPS + i] = A[offj(j0 + k) + i - (j0 + k)];
            }
        }
        __syncthreads();
        if (h == 0) continue;

        // ---- row-parallel TRSM: each thread solves one row of L21 ----
        if (tid < h) {
            const int i = j0 + 16 + tid;
            float y[16];
#pragma unroll
            for (int k = 0; k < 16; k++) y[k] = Lp[k * LPS + i];
#pragma unroll
            for (int k = 0; k < 16; k++) {
                y[k] *= rd[j0 + k];
                const float yk = y[k];
                const float* colk = A + offj(j0 + k);
#pragma unroll
                for (int m = 1; m < 16; m++)
                    if (k + m < 16) y[k + m] -= colk[m] * yk;
            }
#pragma unroll
            for (int k = 0; k < 16; k++) {
                Lp[k * LPS + i] = y[k];
                A[offj(j0 + k) + i - (j0 + k)] = y[k];
            }
        }
        __syncthreads();

        // ---- trailing SYRK: A22 -= L21 L21^T, 8x8 register tiles ----
        const int nb = h >> 3;
        const int ntiles = nb * (nb + 1) / 2;
        for (int t = tid; t < ntiles; t += 512) {
            int bi = (int)((sqrtf(8.f * (float)t + 1.f) - 1.f) * 0.5f);
            while ((bi + 1) * (bi + 2) / 2 <= t) bi++;
            while (bi * (bi + 1) / 2 > t) bi--;
            const int bj = t - bi * (bi + 1) / 2;
            const int i0 = j0 + 16 + 8 * bi, jj0 = j0 + 16 + 8 * bj;
            float acc[8][8];
#pragma unroll
            for (int r = 0; r < 8; r++)
#pragma unroll
                for (int c = 0; c < 8; c++) acc[r][c] = 0.f;
#pragma unroll
            for (int k = 0; k < 16; k++) {
                const float* lk = Lp + k * LPS;
                float4 a0 = *(const float4*)&lk[i0];
                float4 a1 = *(const float4*)&lk[i0 + 4];
                float4 b0 = *(const float4*)&lk[jj0];
                float4 b1 = *(const float4*)&lk[jj0 + 4];
                float ar[8] = {a0.x, a0.y, a0.z, a0.w, a1.x, a1.y, a1.z, a1.w};
                float br[8] = {b0.x, b0.y, b0.z, b0.w, b1.x, b1.y, b1.z, b1.w};
#pragma unroll
                for (int r = 0; r < 8; r++)
#pragma unroll
                    for (int c = 0; c < 8; c++) acc[r][c] += ar[r] * br[c];
            }
#pragma unroll
            for (int c = 0; c < 8; c++) {
                const int j = jj0 + c;
                float* colc = A + offj(j);
#pragma unroll
                for (int r = 0; r < 8; r++) {
                    const int i = i0 + r;
                    if (i >= j) colc[i - j] -= acc[r][c];
                }
            }
        }
        __syncthreads();
    }

    // ---- forward: L y = 1 ----
    for (int r = tid; r < P; r += 512) yv[r] = 1.0f;
    __syncthreads();
    for (int jb = 0; jb < 16; jb++) {
        const int j0 = jb * 16;
        if (tid < 32) {
            const int r = lane;
            float a[16];
#pragma unroll
            for (int c = 0; c < 16; c++)
                a[c] = (r < 16 && r >= c) ? A[offj(j0 + c) + r - c] : 0.f;
            float y   = (r < 16) ? yv[j0 + r] : 0.f;
            float rmy = (r < 16) ? rd[j0 + r] : 0.f;
#pragma unroll
            for (int jj = 0; jj < 16; jj++) {
                if (r == jj) y *= rmy;
                float yjj = __shfl_sync(FULLM, y, jj);
                if (r > jj && r < 16) y -= a[jj] * yjj;
            }
            if (r < 16) yv[j0 + r] = y;
        }
        __syncthreads();
        for (int r = j0 + 16 + tid; r < P; r += 512) {
            float s = 0.f;
#pragma unroll
            for (int jj = 0; jj < 16; jj++)
                s += A[offj(j0 + jj) + r - (j0 + jj)] * yv[j0 + jj];
            yv[r] -= s;
        }
        __syncthreads();
    }

    // ---- backward: L^T z = y ----
    for (int r = tid; r < P; r += 512) zv[r] = yv[r];
    __syncthreads();
    for (int jb = 15; jb >= 0; jb--) {
        const int j0 = jb * 16;
        if (tid < 32) {
            const int c = lane;
            float a[16];
#pragma unroll
            for (int rr = 0; rr < 16; rr++)
                a[rr] = (c < 16 && rr >= c) ? A[offj(j0 + c) + rr - c] : 0.f;
            float z   = (c < 16) ? zv[j0 + c] : 0.f;
            float rmz = (c < 16) ? rd[j0 + c] : 0.f;
#pragma unroll
            for (int jj = 15; jj >= 0; jj--) {
                if (c == jj) z *= rmz;
                float zjj = __shfl_sync(FULLM, z, jj);
                if (c < jj) z -= a[jj] * zjj;
            }
            if (c < 16) zv[j0 + c] = z;
        }
        __syncthreads();
        for (int i = tid; i < j0; i += 512) {
            const float* coli = A + offj(i);
            float s = 0.f;
#pragma unroll
            for (int kk = 0; kk < 16; kk++)
                s += coli[j0 + kk - i] * zv[j0 + kk];
            zv[i] -= s;
        }
        __syncthreads();
    }

    // ---- normalize scale = 256 / sum(z) ----
    float s = (tid < P) ? zv[tid] : 0.f;
#pragma unroll
    for (int o = 16; o > 0; o >>= 1) s += __shfl_down_sync(FULLM, s, o);
    if (lane == 0) red[tid >> 5] = s;
    __syncthreads();
    if (tid == 0) {
        float tot = 0.f;
        for (int k = 0; k < 16; k++) tot += red[k];
        red[40] = 256.0f / tot;
    }
    __syncthreads();
    const float scale = red[40];

    // ---- epilogue: 10 warps x 2 test days each ----
    if (tid < 320) {
        const int ww = tid >> 5;
#pragma unroll
        for (int tt = 0; tt < 2; tt++) {
            const int t = ww * 2 + tt;
            const float* yr = Y + (size_t)((w + 24) * 20 + t) * P;
            float part = 0.f;
#pragma unroll
            for (int q = 0; q < 8; q++)
                part += yr[lane + 32 * q] * zv[lane + 32 * q];
#pragma unroll
            for (int o = 16; o > 0; o >>= 1) part += __shfl_down_sync(FULLM, part, o);
            if (lane == 0) red[t] = part * scale;
        }
    }
    __syncthreads();
    if (tid == 0) {
        float se = 0.f, sq = 0.f;
#pragma unroll
        for (int t = 0; t < 20; t++) { float rt = red[t]; se += rt; sq += rt * rt; }
        g_res[w] = se;
        g_res[NWIN + w] = (sq - se * se / 20.f) / 19.f;
    }
}

// ---------------- K6: final reduction ---------------------------------------
__global__ void k_final(float* out) {
    __shared__ float rb[64];
    const int tid = threadIdx.x;
    float se = 0.f, ss = 0.f;
    for (int w = tid; w < NWIN; w += 256) { se += g_res[w]; ss += g_res[NWIN + w]; }
#pragma unroll
    for (int o = 16; o > 0; o >>= 1) {
        se += __shfl_down_sync(FULLM, se, o);
        ss += __shfl_down_sync(FULLM, ss, o);
    }
    if ((tid & 31) == 0) { rb[tid >> 5] = se; rb[32 + (tid >> 5)] = ss; }
    __syncthreads();
    if (tid == 0) {
        float te = 0.f, ts = 0.f;
        for (int k = 0; k < 8; k++) { te += rb[k]; ts += rb[32 + k]; }
        float mu  = te / (float)NWIN / 20.f * 252.f;
        float vol = sqrtf(ts / (float)NWIN * 252.f);
        out[0] = vol;
        out[1] = mu;
        out[2] = mu / vol;
    }
}

extern "C" void kernel_launch(void* const* d_in, const int* in_sizes, int n_in,
                              void* d_out, int out_size) {
    const float* Y = (const float*)d_in[0];
    const float* a = (const float*)d_in[1];
    cudaFuncSetAttribute(k_chol, cudaFuncAttributeMaxDynamicSharedMemorySize, CHOL_SMEM);
    k_setup<<<1, 1>>>(a);
    k_gram<<<NBLK * 10, 256>>>(Y);
    k_vsum<<<NBLK, 256>>>(Y);
    k_mean<<<NWIN, 256>>>();
    dim3 gs((TRI + 255) / 256, SIG_NCHUNK);
    k_sigma<<<gs, 256>>>();
    k_chol<<<NWIN, 512, CHOL_SMEM>>>(Y);
    k_final<<<1, 256>>>((float*)d_out);
}

// round 5
// speedup vs baseline: 1.5809x; 1.0692x over previous
#include <cuda_runtime.h>
#include <math.h>

#define P        256
#define NT       480
#define NBLK     1000
#define NWIN     976
#define TRI      32896        // P*(P+1)/2
#define SIG_CHUNK  61
#define SIG_NCHUNK 16
#define LPS      288          // padded Lp row stride (floats)
#define CHOL_SMEM ((TRI + 16*LPS + 256 + 256 + 256 + 64) * 4)
#define FULLM 0xffffffffu

__device__ float g_wc[64];
__device__ float g_H[(size_t)NBLK * TRI];
__device__ float g_Sigma[(size_t)NWIN * TRI];
__device__ float g_V[NBLK * P];
__device__ float g_mean[NWIN * P];
__device__ float g_res[2 * NWIN];

__device__ __forceinline__ int offj(int j) { return j * P - ((j * (j - 1)) >> 1); }

// ---------------- K0: weights & constants ---------------------------------
__global__ void k_setup(const float* __restrict__ a_in) {
    double a = (double)a_in[0];
    double s1 = 0.0, ap = 1.0;
    for (int u = 0; u < NT; u++) { s1 += ap; ap *= a; }
    double c = (double)NT / s1;
    double s2 = 0.0, a2 = a * a; ap = 1.0;
    for (int u = 0; u < NT; u++) { s2 += ap; ap *= a2; }
    s2 *= c * c;
    double denom = (double)NT - s2 / (double)NT;
    for (int k = 0; k < 24; k++) g_wc[k]      = (float)pow(a, 20.0 * (23 - k));
    for (int u = 0; u < 20; u++) g_wc[24 + u] = (float)pow(a, (double)(19 - u));
    g_wc[44] = (float)c;
    g_wc[45] = (float)(1.0 / denom);
    g_wc[46] = (float)pow(a, 20.0);
    g_wc[47] = (float)pow(a, 460.0);
    g_wc[48] = (float)(c / (double)NT);
}

// ---------------- K1: block Grams (packed lower) ---------------------------
__global__ void __launch_bounds__(256) k_gram(const float* __restrict__ Y) {
    const int lt = blockIdx.x % 10;
    const int b  = blockIdx.x / 10;
    int ti = 0;
    while (((ti + 1) * (ti + 2)) / 2 <= lt) ti++;
    const int tj = lt - (ti * (ti + 1)) / 2;

    __shared__ __align__(16) float As[20][64];
    __shared__ __align__(16) float Bs[20][64];
    __shared__ float Cs[64][65];
    const int tid = threadIdx.x;
    for (int idx = tid; idx < 20 * 64; idx += 256) {
        int u = idx >> 6, cc = idx & 63;
        size_t row = (size_t)(b * 20 + u) * P;
        As[u][cc] = g_wc[24 + u] * Y[row + ti * 64 + cc];
        Bs[u][cc] = Y[row + tj * 64 + cc];
    }
    __syncthreads();

    const int tx = tid & 15, ty = tid >> 4;
    float acc[4][4];
#pragma unroll
    for (int r = 0; r < 4; r++)
#pragma unroll
        for (int c = 0; c < 4; c++) acc[r][c] = 0.f;

#pragma unroll
    for (int u = 0; u < 20; u++) {
        float4 av = *(const float4*)&As[u][ty * 4];
        float4 bv = *(const float4*)&Bs[u][tx * 4];
        float ar[4] = {av.x, av.y, av.z, av.w};
        float br[4] = {bv.x, bv.y, bv.z, bv.w};
#pragma unroll
        for (int r = 0; r < 4; r++)
#pragma unroll
            for (int c = 0; c < 4; c++) acc[r][c] += ar[r] * br[c];
    }
#pragma unroll
    for (int r = 0; r < 4; r++)
#pragma unroll
        for (int c = 0; c < 4; c++) Cs[ty * 4 + r][tx * 4 + c] = acc[r][c];
    __syncthreads();

    float* Hb = g_H + (size_t)b * TRI;
    for (int idx = tid; idx < 64 * 64; idx += 256) {
        int cc = idx >> 6, rr = idx & 63;
        if (ti == tj && rr < cc) continue;
        int j = tj * 64 + cc, i = ti * 64 + rr;
        Hb[offj(j) + i - j] = Cs[rr][cc];
    }
}

// ---------------- K2: weighted block row-sums ------------------------------
__global__ void k_vsum(const float* __restrict__ Y) {
    const int b = blockIdx.x, i = threadIdx.x;
    float s = 0.f;
#pragma unroll
    for (int u = 0; u < 20; u++)
        s += g_wc[24 + u] * Y[(size_t)(b * 20 + u) * P + i];
    g_V[b * P + i] = s;
}

// ---------------- K3: per-window means --------------------------------------
__global__ void k_mean() {
    const int w = blockIdx.x, i = threadIdx.x;
    float s = 0.f;
#pragma unroll
    for (int k = 0; k < 24; k++)
        s += g_wc[k] * g_V[(w + k) * P + i];
    g_mean[w * P + i] = s * g_wc[48];
}

// ---------------- K4: Sigma via sliding recurrence --------------------------
__global__ void k_sigma() {
    int e = blockIdx.x * 256 + threadIdx.x;
    if (e >= TRI) return;
    int c = blockIdx.y;
    int j = (int)((513.0 - sqrt(513.0 * 513.0 - 8.0 * (double)e)) * 0.5);
    if (j < 0) j = 0; if (j > 255) j = 255;
    while (j < 255 && offj(j + 1) <= e) j++;
    while (j > 0 && offj(j) > e) j--;
    int i = e - offj(j) + j;

    const float a20 = g_wc[46], gg0 = g_wc[47], cw = g_wc[44], inv = g_wc[45];
    const int w0 = c * SIG_CHUNK;
    float T = 0.f;
    for (int k = 0; k < 24; k++) T += g_wc[k] * g_H[(size_t)(w0 + k) * TRI + e];
    for (int s = 0; s < SIG_CHUNK; s++) {
        int w = w0 + s;
        float m = g_mean[w * P + i] * g_mean[w * P + j];
        g_Sigma[(size_t)w * TRI + e] = (cw * T - 480.0f * m) * inv;
        if (s + 1 < SIG_CHUNK)
            T = a20 * (T - gg0 * g_H[(size_t)w * TRI + e]) + g_H[(size_t)(w + 24) * TRI + e];
    }
}

// ---------------- K5: batched packed Cholesky + solves + epilogue -----------
__global__ void __launch_bounds__(512, 1) k_chol(const float* __restrict__ Y) {
    extern __shared__ float sm[];
    float* A   = sm;                    // TRI packed col-major lower
    float* Lp  = sm + TRI;              // 16 x LPS, k-major panel
    float* yv  = Lp + 16 * LPS;         // 256
    float* zv  = yv + 256;              // 256
    float* rd  = zv + 256;              // 256: 1/L[j][j]
    float* red = rd + 256;              // 64 scratch
    const int w = blockIdx.x;
    const int tid = threadIdx.x;
    const int lane = tid & 31;
    const int wid  = tid >> 5;

    { // load Sigma (float4)
        const float4* src = (const float4*)(g_Sigma + (size_t)w * TRI);
        float4* dst = (float4*)A;
        for (int idx = tid; idx < TRI / 4; idx += 512) dst[idx] = src[idx];
    }
    __syncthreads();

    for (int kb = 0; kb < 16; kb++) {
        const int j0 = kb * 16;
        const int h  = P - (j0 + 16);
        const int s0 = j0 + 16;

        // ---- warp 0: register Cholesky of 16x16 diag block;
        //      warps 1..15: stage sub-panel k-major ----
        if (tid < 32) {
            const int r = lane;
            float a[16];
#pragma unroll
            for (int c = 0; c < 16; c++)
                a[c] = (r >= c) ? A[offj(j0 + c) + r - c] : 0.f;
#pragma unroll
            for (int jj = 0; jj < 16; jj++) {
                float d = __shfl_sync(FULLM, a[jj], jj);
                float rinv = rsqrtf(d);
                if (r == jj) rd[j0 + jj] = rinv;
                a[jj] *= rinv;
#pragma unroll
                for (int c = jj + 1; c < 16; c++) {
                    float Lcjj = __shfl_sync(FULLM, a[jj], c);
                    if (r >= c) a[c] -= a[jj] * Lcjj;
                }
            }
#pragma unroll
            for (int c = 0; c < 16; c++)
                if (r >= c) A[offj(j0 + c) + r - c] = a[c];
        } else if (h > 0) {
            for (int idx = tid - 32; idx < 16 * h; idx += 480) {
                int k = idx / h, rr = idx - k * h;
                int i = s0 + rr;
                Lp[k * LPS + i] = A[offj(j0 + k) + i - (j0 + k)];
            }
        }
        __syncthreads();
        if (h == 0) continue;

        // ---- row-parallel TRSM: each thread solves one row of L21 ----
        if (tid < h) {
            const int i = s0 + tid;
            float y[16];
#pragma unroll
            for (int k = 0; k < 16; k++) y[k] = Lp[k * LPS + i];
#pragma unroll
            for (int k = 0; k < 16; k++) {
                y[k] *= rd[j0 + k];
                const float yk = y[k];
                const float* colk = A + offj(j0 + k);
#pragma unroll
                for (int m = 1; m < 16; m++)
                    if (k + m < 16) y[k + m] -= colk[m] * yk;
            }
#pragma unroll
            for (int k = 0; k < 16; k++) {
                Lp[k * LPS + i] = y[k];
                A[offj(j0 + k) + i - (j0 + k)] = y[k];
            }
        }
        __syncthreads();

        // ---- trailing SYRK: cooperative 32x32 warp macro-tiles --------------
        // lane grid 4(i) x 8(j); lane computes 8 rows x 4 cols.
        // a-loads: 4 distinct addrs + broadcast; b-load: contiguous 128B.
        {
            const int mt = (h + 31) >> 5;
            const int ntile = mt * (mt + 1) / 2;
            const int li = lane & 3, lj = lane >> 2;
            for (int t = wid; t < ntile; t += 16) {
                int bi_ = (int)((sqrtf(8.f * (float)t + 1.f) - 1.f) * 0.5f);
                while ((bi_ + 1) * (bi_ + 2) / 2 <= t) bi_++;
                while (bi_ * (bi_ + 1) / 2 > t) bi_--;
                const int bj_ = t - bi_ * (bi_ + 1) / 2;
                const int i0  = s0 + 32 * bi_ + 8 * li;
                const int jc0 = s0 + 32 * bj_ + 4 * lj;
                float acc[8][4];
#pragma unroll
                for (int r = 0; r < 8; r++)
#pragma unroll
                    for (int c = 0; c < 4; c++) acc[r][c] = 0.f;
#pragma unroll
                for (int k = 0; k < 16; k++) {
                    const float* lk = Lp + k * LPS;
                    float4 a0 = *(const float4*)&lk[i0];
                    float4 a1 = *(const float4*)&lk[i0 + 4];
                    float4 bv = *(const float4*)&lk[jc0];
                    float ar[8] = {a0.x, a0.y, a0.z, a0.w, a1.x, a1.y, a1.z, a1.w};
                    float br[4] = {bv.x, bv.y, bv.z, bv.w};
#pragma unroll
                    for (int r = 0; r < 8; r++)
#pragma unroll
                        for (int c = 0; c < 4; c++) acc[r][c] = fmaf(ar[r], br[c], acc[r][c]);
                }
#pragma unroll
                for (int c = 0; c < 4; c++) {
                    const int j = jc0 + c;
                    if (j < P) {
                        float* colc = A + offj(j);
#pragma unroll
                        for (int r = 0; r < 8; r++) {
                            const int i = i0 + r;
                            if (i < P && i >= j) colc[i - j] -= acc[r][c];
                        }
                    }
                }
            }
        }
        __syncthreads();
    }

    // ---- forward: L y = 1 ----
    for (int r = tid; r < P; r += 512) yv[r] = 1.0f;
    __syncthreads();
    for (int jb = 0; jb < 16; jb++) {
        const int j0 = jb * 16;
        if (tid < 32) {
            const int r = lane;
            float a[16];
#pragma unroll
            for (int c = 0; c < 16; c++)
                a[c] = (r < 16 && r >= c) ? A[offj(j0 + c) + r - c] : 0.f;
            float y   = (r < 16) ? yv[j0 + r] : 0.f;
            float rmy = (r < 16) ? rd[j0 + r] : 0.f;
#pragma unroll
            for (int jj = 0; jj < 16; jj++) {
                if (r == jj) y *= rmy;
                float yjj = __shfl_sync(FULLM, y, jj);
                if (r > jj && r < 16) y -= a[jj] * yjj;
            }
            if (r < 16) yv[j0 + r] = y;
        }
        __syncthreads();
        for (int r = j0 + 16 + tid; r < P; r += 512) {
            float s = 0.f;
#pragma unroll
            for (int jj = 0; jj < 16; jj++)
                s += A[offj(j0 + jj) + r - (j0 + jj)] * yv[j0 + jj];
            yv[r] -= s;
        }
        __syncthreads();
    }

    // ---- backward: L^T z = y ----
    for (int r = tid; r < P; r += 512) zv[r] = yv[r];
    __syncthreads();
    for (int jb = 15; jb >= 0; jb--) {
        const int j0 = jb * 16;
        if (tid < 32) {
            const int c = lane;
            float a[16];
#pragma unroll
            for (int rr = 0; rr < 16; rr++)
                a[rr] = (c < 16 && rr >= c) ? A[offj(j0 + c) + rr - c] : 0.f;
            float z   = (c < 16) ? zv[j0 + c] : 0.f;
            float rmz = (c < 16) ? rd[j0 + c] : 0.f;
#pragma unroll
            for (int jj = 15; jj >= 0; jj--) {
                if (c == jj) z *= rmz;
                float zjj = __shfl_sync(FULLM, z, jj);
                if (c < jj) z -= a[jj] * zjj;
            }
            if (c < 16) zv[j0 + c] = z;
        }
        __syncthreads();
        for (int i = tid; i < j0; i += 512) {
            const float* coli = A + offj(i);
            float s = 0.f;
#pragma unroll
            for (int kk = 0; kk < 16; kk++)
                s += coli[j0 + kk - i] * zv[j0 + kk];
            zv[i] -= s;
        }
        __syncthreads();
    }

    // ---- normalize scale = 256 / sum(z) ----
    float s = (tid < P) ? zv[tid] : 0.f;
#pragma unroll
    for (int o = 16; o > 0; o >>= 1) s += __shfl_down_sync(FULLM, s, o);
    if (lane == 0) red[tid >> 5] = s;
    __syncthreads();
    if (tid == 0) {
        float tot = 0.f;
        for (int k = 0; k < 16; k++) tot += red[k];
        red[40] = 256.0f / tot;
    }
    __syncthreads();
    const float scale = red[40];

    // ---- epilogue: 10 warps x 2 test days each ----
    if (tid < 320) {
        const int ww = tid >> 5;
#pragma unroll
        for (int tt = 0; tt < 2; tt++) {
            const int t = ww * 2 + tt;
            const float* yr = Y + (size_t)((w + 24) * 20 + t) * P;
            float part = 0.f;
#pragma unroll
            for (int q = 0; q < 8; q++)
                part += yr[lane + 32 * q] * zv[lane + 32 * q];
#pragma unroll
            for (int o = 16; o > 0; o >>= 1) part += __shfl_down_sync(FULLM, part, o);
            if (lane == 0) red[t] = part * scale;
        }
    }
    __syncthreads();
    if (tid == 0) {
        float se = 0.f, sq = 0.f;
#pragma unroll
        for (int t = 0; t < 20; t++) { float rt = red[t]; se += rt; sq += rt * rt; }
        g_res[w] = se;
        g_res[NWIN + w] = (sq - se * se / 20.f) / 19.f;
    }
}

// ---------------- K6: final reduction ---------------------------------------
__global__ void k_final(float* out) {
    __shared__ float rb[64];
    const int tid = threadIdx.x;
    float se = 0.f, ss = 0.f;
    for (int w = tid; w < NWIN; w += 256) { se += g_res[w]; ss += g_res[NWIN + w]; }
#pragma unroll
    for (int o = 16; o > 0; o >>= 1) {
        se += __shfl_down_sync(FULLM, se, o);
        ss += __shfl_down_sync(FULLM, ss, o);
    }
    if ((tid & 31) == 0) { rb[tid >> 5] = se; rb[32 + (tid >> 5)] = ss; }
    __syncthreads();
    if (tid == 0) {
        float te = 0.f, ts = 0.f;
        for (int k = 0; k < 8; k++) { te += rb[k]; ts += rb[32 + k]; }
        float mu  = te / (float)NWIN / 20.f * 252.f;
        float vol = sqrtf(ts / (float)NWIN * 252.f);
        out[0] = vol;
        out[1] = mu;
        out[2] = mu / vol;
    }
}

extern "C" void kernel_launch(void* const* d_in, const int* in_sizes, int n_in,
                              void* d_out, int out_size) {
    const float* Y = (const float*)d_in[0];
    const float* a = (const float*)d_in[1];
    cudaFuncSetAttribute(k_chol, cudaFuncAttributeMaxDynamicSharedMemorySize, CHOL_SMEM);
    k_setup<<<1, 1>>>(a);
    k_gram<<<NBLK * 10, 256>>>(Y);
    k_vsum<<<NBLK, 256>>>(Y);
    k_mean<<<NWIN, 256>>>();
    dim3 gs((TRI + 255) / 256, SIG_NCHUNK);
    k_sigma<<<gs, 256>>>();
    k_chol<<<NWIN, 512, CHOL_SMEM>>>(Y);
    k_final<<<1, 256>>>((float*)d_out);
}

// round 6
// speedup vs baseline: 1.6329x; 1.0329x over previous
#include <cuda_runtime.h>
#include <math.h>

#define P        256
#define NT       480
#define NBLK     1000
#define NWIN     976
#define TRI      32896        // P*(P+1)/2
#define SIG_CHUNK  61
#define SIG_NCHUNK 16
#define LPS      288          // padded Lp row stride (floats)
#define CHOL_SMEM ((TRI + 2*16*LPS + 256 + 256 + 256 + 64) * 4)
#define FULLM 0xffffffffu

__device__ float g_wc[64];
__device__ float g_H[(size_t)NBLK * TRI];
__device__ float g_Sigma[(size_t)NWIN * TRI];
__device__ float g_V[NBLK * P];
__device__ float g_mean[NWIN * P];
__device__ float g_res[2 * NWIN];

__device__ __forceinline__ int offj(int j) { return j * P - ((j * (j - 1)) >> 1); }

// ---------------- K0: weights & constants ---------------------------------
__global__ void k_setup(const float* __restrict__ a_in) {
    double a = (double)a_in[0];
    double s1 = 0.0, ap = 1.0;
    for (int u = 0; u < NT; u++) { s1 += ap; ap *= a; }
    double c = (double)NT / s1;
    double s2 = 0.0, a2 = a * a; ap = 1.0;
    for (int u = 0; u < NT; u++) { s2 += ap; ap *= a2; }
    s2 *= c * c;
    double denom = (double)NT - s2 / (double)NT;
    for (int k = 0; k < 24; k++) g_wc[k]      = (float)pow(a, 20.0 * (23 - k));
    for (int u = 0; u < 20; u++) g_wc[24 + u] = (float)pow(a, (double)(19 - u));
    g_wc[44] = (float)c;
    g_wc[45] = (float)(1.0 / denom);
    g_wc[46] = (float)pow(a, 20.0);
    g_wc[47] = (float)pow(a, 460.0);
    g_wc[48] = (float)(c / (double)NT);
}

// ---------------- K1: block Grams (packed lower) ---------------------------
__global__ void __launch_bounds__(256) k_gram(const float* __restrict__ Y) {
    const int lt = blockIdx.x % 10;
    const int b  = blockIdx.x / 10;
    int ti = 0;
    while (((ti + 1) * (ti + 2)) / 2 <= lt) ti++;
    const int tj = lt - (ti * (ti + 1)) / 2;

    __shared__ __align__(16) float As[20][64];
    __shared__ __align__(16) float Bs[20][64];
    __shared__ float Cs[64][65];
    const int tid = threadIdx.x;
    for (int idx = tid; idx < 20 * 64; idx += 256) {
        int u = idx >> 6, cc = idx & 63;
        size_t row = (size_t)(b * 20 + u) * P;
        As[u][cc] = g_wc[24 + u] * Y[row + ti * 64 + cc];
        Bs[u][cc] = Y[row + tj * 64 + cc];
    }
    __syncthreads();

    const int tx = tid & 15, ty = tid >> 4;
    float acc[4][4];
#pragma unroll
    for (int r = 0; r < 4; r++)
#pragma unroll
        for (int c = 0; c < 4; c++) acc[r][c] = 0.f;

#pragma unroll
    for (int u = 0; u < 20; u++) {
        float4 av = *(const float4*)&As[u][ty * 4];
        float4 bv = *(const float4*)&Bs[u][tx * 4];
        float ar[4] = {av.x, av.y, av.z, av.w};
        float br[4] = {bv.x, bv.y, bv.z, bv.w};
#pragma unroll
        for (int r = 0; r < 4; r++)
#pragma unroll
            for (int c = 0; c < 4; c++) acc[r][c] += ar[r] * br[c];
    }
#pragma unroll
    for (int r = 0; r < 4; r++)
#pragma unroll
        for (int c = 0; c < 4; c++) Cs[ty * 4 + r][tx * 4 + c] = acc[r][c];
    __syncthreads();

    float* Hb = g_H + (size_t)b * TRI;
    for (int idx = tid; idx < 64 * 64; idx += 256) {
        int cc = idx >> 6, rr = idx & 63;
        if (ti == tj && rr < cc) continue;
        int j = tj * 64 + cc, i = ti * 64 + rr;
        Hb[offj(j) + i - j] = Cs[rr][cc];
    }
}

// ---------------- K2: weighted block row-sums ------------------------------
__global__ void k_vsum(const float* __restrict__ Y) {
    const int b = blockIdx.x, i = threadIdx.x;
    float s = 0.f;
#pragma unroll
    for (int u = 0; u < 20; u++)
        s += g_wc[24 + u] * Y[(size_t)(b * 20 + u) * P + i];
    g_V[b * P + i] = s;
}

// ---------------- K3: per-window means --------------------------------------
__global__ void k_mean() {
    const int w = blockIdx.x, i = threadIdx.x;
    float s = 0.f;
#pragma unroll
    for (int k = 0; k < 24; k++)
        s += g_wc[k] * g_V[(w + k) * P + i];
    g_mean[w * P + i] = s * g_wc[48];
}

// ---------------- K4: Sigma via sliding recurrence --------------------------
__global__ void k_sigma() {
    int e = blockIdx.x * 256 + threadIdx.x;
    if (e >= TRI) return;
    int c = blockIdx.y;
    int j = (int)((513.0 - sqrt(513.0 * 513.0 - 8.0 * (double)e)) * 0.5);
    if (j < 0) j = 0; if (j > 255) j = 255;
    while (j < 255 && offj(j + 1) <= e) j++;
    while (j > 0 && offj(j) > e) j--;
    int i = e - offj(j) + j;

    const float a20 = g_wc[46], gg0 = g_wc[47], cw = g_wc[44], inv = g_wc[45];
    const int w0 = c * SIG_CHUNK;
    float T = 0.f;
    for (int k = 0; k < 24; k++) T += g_wc[k] * g_H[(size_t)(w0 + k) * TRI + e];
    for (int s = 0; s < SIG_CHUNK; s++) {
        int w = w0 + s;
        float m = g_mean[w * P + i] * g_mean[w * P + j];
        g_Sigma[(size_t)w * TRI + e] = (cw * T - 480.0f * m) * inv;
        if (s + 1 < SIG_CHUNK)
            T = a20 * (T - gg0 * g_H[(size_t)w * TRI + e]) + g_H[(size_t)(w + 24) * TRI + e];
    }
}

// ---- device helpers for k_chol ---------------------------------------------
__device__ __forceinline__ void diag_chol16(float* A, float* rd, int j0, int lane) {
    const int r = lane;
    float a[16];
#pragma unroll
    for (int c = 0; c < 16; c++)
        a[c] = (r >= c) ? A[offj(j0 + c) + r - c] : 0.f;
#pragma unroll
    for (int jj = 0; jj < 16; jj++) {
        float d = __shfl_sync(FULLM, a[jj], jj);
        float rinv = rsqrtf(d);
        if (r == jj) rd[j0 + jj] = rinv;
        a[jj] *= rinv;
#pragma unroll
        for (int c = jj + 1; c < 16; c++) {
            float Lcjj = __shfl_sync(FULLM, a[jj], c);
            if (r >= c) a[c] -= a[jj] * Lcjj;
        }
    }
#pragma unroll
    for (int c = 0; c < 16; c++)
        if (r >= c) A[offj(j0 + c) + r - c] = a[c];
}

__device__ __forceinline__ void trsm_row(float* A, const float* rd, float* Lp,
                                         int j0, int i) {
    float y[16];
#pragma unroll
    for (int k = 0; k < 16; k++) y[k] = Lp[k * LPS + i];
#pragma unroll
    for (int k = 0; k < 16; k++) {
        y[k] *= rd[j0 + k];
        const float yk = y[k];
        const float* colk = A + offj(j0 + k);
#pragma unroll
        for (int m = 1; m < 16; m++)
            if (k + m < 16) y[k + m] -= colk[m] * yk;
    }
#pragma unroll
    for (int k = 0; k < 16; k++) {
        Lp[k * LPS + i] = y[k];
        A[offj(j0 + k) + i - (j0 + k)] = y[k];
    }
}

// ---------------- K5: lookahead-pipelined Cholesky + solves + epilogue ------
__global__ void __launch_bounds__(512, 1) k_chol(const float* __restrict__ Y) {
    extern __shared__ float sm[];
    float* A    = sm;                     // TRI packed col-major lower
    float* Lp0  = sm + TRI;               // panel buffer 0
    float* Lp1  = Lp0 + 16 * LPS;         // panel buffer 1
    float* yv   = Lp1 + 16 * LPS;         // 256
    float* zv   = yv + 256;               // 256
    float* rd   = zv + 256;               // 256: 1/L[j][j]
    float* red  = rd + 256;               // 64 scratch
    const int w = blockIdx.x;
    const int tid = threadIdx.x;
    const int lane = tid & 31;
    const int wid  = tid >> 5;

    { // load Sigma (float4)
        const float4* src = (const float4*)(g_Sigma + (size_t)w * TRI);
        float4* dst = (float4*)A;
        for (int idx = tid; idx < TRI / 4; idx += 512) dst[idx] = src[idx];
    }
    __syncthreads();

    // ---- prologue: factor + TRSM panel 0 (all threads) ----
    if (tid < 32) {
        diag_chol16(A, rd, 0, lane);
    } else {
        for (int k = (tid - 32) / 30; k < 16; k += 16) { /* placeholder */ }
        // stage panel 0 rows 16..255 into Lp0 (480 threads)
        for (int k = 0; k < 16; k++)
            for (int rr = tid - 32; rr < 240; rr += 480)
                Lp0[k * LPS + 16 + rr] = A[offj(k) + 16 + rr - k];
    }
    __syncthreads();
    if (tid < 240) trsm_row(A, rd, Lp0, 0, 16 + tid);
    __syncthreads();

    // ---- main lookahead loop ----
    for (int kb = 0; kb < 15; kb++) {
        float* bufc = (kb & 1) ? Lp1 : Lp0;   // panel kb (TRSM'd)
        float* bufn = (kb & 1) ? Lp0 : Lp1;   // panel kb+1 (to stage)
        const int s0  = 16 * (kb + 1);        // strip cols / next diag start
        const int s0n = s0 + 16;              // next panel subdiag start
        const int hp  = P - s0n;              // next panel subdiag height

        // ---- strip-SYRK: apply panel kb to cols [s0, s0+16), all threads ----
        {
            const int hs = P - s0;
            const int half = tid & 1;
            const int bj0 = s0 + half * 8;
            for (int r = tid >> 1; r < hs; r += 256) {
                const int i = s0 + r;
                float acc[8];
#pragma unroll
                for (int c = 0; c < 8; c++) acc[c] = 0.f;
#pragma unroll
                for (int k = 0; k < 16; k++) {
                    const float* lk = bufc + k * LPS;
                    float av = lk[i];
                    float4 b0 = *(const float4*)&lk[bj0];
                    float4 b1 = *(const float4*)&lk[bj0 + 4];
                    float br[8] = {b0.x, b0.y, b0.z, b0.w, b1.x, b1.y, b1.z, b1.w};
#pragma unroll
                    for (int c = 0; c < 8; c++) acc[c] = fmaf(av, br[c], acc[c]);
                }
#pragma unroll
                for (int c = 0; c < 8; c++) {
                    const int j = bj0 + c;
                    if (i >= j) A[offj(j) + i - j] -= acc[c];
                }
            }
        }
        __syncthreads();

        // ---- concurrent: panel team (warps 0-3) | update team (warps 4-15) ----
        if (wid < 4) {
            if (wid == 0) {
                diag_chol16(A, rd, s0, lane);
            } else {
                // warps 1-3 (96 threads) stage next panel subdiag into bufn
                const int st = tid - 32;
                for (int k = 0; k < 16; k++)
                    for (int rr = st; rr < hp; rr += 96)
                        bufn[k * LPS + s0n + rr] = A[offj(s0 + k) + s0n + rr - (s0 + k)];
            }
            asm volatile("bar.sync 1, 128;" ::: "memory");
            for (int r = tid; r < hp; r += 128)
                trsm_row(A, rd, bufn, s0, s0n + r);
        } else if (hp > 0) {
            // bulk SYRK: apply panel kb to cols [s0n, P), 32x32 macro-tiles
            const int mt = (hp + 31) >> 5;
            const int ntile = mt * (mt + 1) / 2;
            const int li = lane & 3, lj = lane >> 2;
            for (int t = wid - 4; t < ntile; t += 12) {
                int bi_ = (int)((sqrtf(8.f * (float)t + 1.f) - 1.f) * 0.5f);
                while ((bi_ + 1) * (bi_ + 2) / 2 <= t) bi_++;
                while (bi_ * (bi_ + 1) / 2 > t) bi_--;
                const int bj_ = t - bi_ * (bi_ + 1) / 2;
                const int i0  = s0n + 32 * bi_ + 8 * li;
                const int jc0 = s0n + 32 * bj_ + 4 * lj;
                float acc[8][4];
#pragma unroll
                for (int r = 0; r < 8; r++)
#pragma unroll
                    for (int c = 0; c < 4; c++) acc[r][c] = 0.f;
#pragma unroll
                for (int k = 0; k < 16; k++) {
                    const float* lk = bufc + k * LPS;
                    float4 a0 = *(const float4*)&lk[i0];
                    float4 a1 = *(const float4*)&lk[i0 + 4];
                    float4 bv = *(const float4*)&lk[jc0];
                    float ar[8] = {a0.x, a0.y, a0.z, a0.w, a1.x, a1.y, a1.z, a1.w};
                    float br[4] = {bv.x, bv.y, bv.z, bv.w};
#pragma unroll
                    for (int r = 0; r < 8; r++)
#pragma unroll
                        for (int c = 0; c < 4; c++) acc[r][c] = fmaf(ar[r], br[c], acc[r][c]);
                }
#pragma unroll
                for (int c = 0; c < 4; c++) {
                    const int j = jc0 + c;
                    if (j < P) {
                        float* colc = A + offj(j);
#pragma unroll
                        for (int r = 0; r < 8; r++) {
                            const int i = i0 + r;
                            if (i < P && i >= j) colc[i - j] -= acc[r][c];
                        }
                    }
                }
            }
        }
        __syncthreads();
    }

    // ---- forward: L y = 1 ----
    for (int r = tid; r < P; r += 512) yv[r] = 1.0f;
    __syncthreads();
    for (int jb = 0; jb < 16; jb++) {
        const int j0 = jb * 16;
        if (tid < 32) {
            const int r = lane;
            float a[16];
#pragma unroll
            for (int c = 0; c < 16; c++)
                a[c] = (r < 16 && r >= c) ? A[offj(j0 + c) + r - c] : 0.f;
            float y   = (r < 16) ? yv[j0 + r] : 0.f;
            float rmy = (r < 16) ? rd[j0 + r] : 0.f;
#pragma unroll
            for (int jj = 0; jj < 16; jj++) {
                if (r == jj) y *= rmy;
                float yjj = __shfl_sync(FULLM, y, jj);
                if (r > jj && r < 16) y -= a[jj] * yjj;
            }
            if (r < 16) yv[j0 + r] = y;
        }
        __syncthreads();
        for (int r = j0 + 16 + tid; r < P; r += 512) {
            float s = 0.f;
#pragma unroll
            for (int jj = 0; jj < 16; jj++)
                s += A[offj(j0 + jj) + r - (j0 + jj)] * yv[j0 + jj];
            yv[r] -= s;
        }
        __syncthreads();
    }

    // ---- backward: L^T z = y ----
    for (int r = tid; r < P; r += 512) zv[r] = yv[r];
    __syncthreads();
    for (int jb = 15; jb >= 0; jb--) {
        const int j0 = jb * 16;
        if (tid < 32) {
            const int c = lane;
            float a[16];
#pragma unroll
            for (int rr = 0; rr < 16; rr++)
                a[rr] = (c < 16 && rr >= c) ? A[offj(j0 + c) + rr - c] : 0.f;
            float z   = (c < 16) ? zv[j0 + c] : 0.f;
            float rmz = (c < 16) ? rd[j0 + c] : 0.f;
#pragma unroll
            for (int jj = 15; jj >= 0; jj--) {
                if (c == jj) z *= rmz;
                float zjj = __shfl_sync(FULLM, z, jj);
                if (c < jj) z -= a[jj] * zjj;
            }
            if (c < 16) zv[j0 + c] = z;
        }
        __syncthreads();
        for (int i = tid; i < j0; i += 512) {
            const float* coli = A + offj(i);
            float s = 0.f;
#pragma unroll
            for (int kk = 0; kk < 16; kk++)
                s += coli[j0 + kk - i] * zv[j0 + kk];
            zv[i] -= s;
        }
        __syncthreads();
    }

    // ---- normalize scale = 256 / sum(z) ----
    float s = (tid < P) ? zv[tid] : 0.f;
#pragma unroll
    for (int o = 16; o > 0; o >>= 1) s += __shfl_down_sync(FULLM, s, o);
    if (lane == 0) red[tid >> 5] = s;
    __syncthreads();
    if (tid == 0) {
        float tot = 0.f;
        for (int k = 0; k < 16; k++) tot += red[k];
        red[40] = 256.0f / tot;
    }
    __syncthreads();
    const float scale = red[40];

    // ---- epilogue: 10 warps x 2 test days each ----
    if (tid < 320) {
        const int ww = tid >> 5;
#pragma unroll
        for (int tt = 0; tt < 2; tt++) {
            const int t = ww * 2 + tt;
            const float* yr = Y + (size_t)((w + 24) * 20 + t) * P;
            float part = 0.f;
#pragma unroll
            for (int q = 0; q < 8; q++)
                part += yr[lane + 32 * q] * zv[lane + 32 * q];
#pragma unroll
            for (int o = 16; o > 0; o >>= 1) part += __shfl_down_sync(FULLM, part, o);
            if (lane == 0) red[t] = part * scale;
        }
    }
    __syncthreads();
    if (tid == 0) {
        float se = 0.f, sq = 0.f;
#pragma unroll
        for (int t = 0; t < 20; t++) { float rt = red[t]; se += rt; sq += rt * rt; }
        g_res[w] = se;
        g_res[NWIN + w] = (sq - se * se / 20.f) / 19.f;
    }
}

// ---------------- K6: final reduction ---------------------------------------
__global__ void k_final(float* out) {
    __shared__ float rb[64];
    const int tid = threadIdx.x;
    float se = 0.f, ss = 0.f;
    for (int w = tid; w < NWIN; w += 256) { se += g_res[w]; ss += g_res[NWIN + w]; }
#pragma unroll
    for (int o = 16; o > 0; o >>= 1) {
        se += __shfl_down_sync(FULLM, se, o);
        ss += __shfl_down_sync(FULLM, ss, o);
    }
    if ((tid & 31) == 0) { rb[tid >> 5] = se; rb[32 + (tid >> 5)] = ss; }
    __syncthreads();
    if (tid == 0) {
        float te = 0.f, ts = 0.f;
        for (int k = 0; k < 8; k++) { te += rb[k]; ts += rb[32 + k]; }
        float mu  = te / (float)NWIN / 20.f * 252.f;
        float vol = sqrtf(ts / (float)NWIN * 252.f);
        out[0] = vol;
        out[1] = mu;
        out[2] = mu / vol;
    }
}

extern "C" void kernel_launch(void* const* d_in, const int* in_sizes, int n_in,
                              void* d_out, int out_size) {
    const float* Y = (const float*)d_in[0];
    const float* a = (const float*)d_in[1];
    cudaFuncSetAttribute(k_chol, cudaFuncAttributeMaxDynamicSharedMemorySize, CHOL_SMEM);
    k_setup<<<1, 1>>>(a);
    k_gram<<<NBLK * 10, 256>>>(Y);
    k_vsum<<<NBLK, 256>>>(Y);
    k_mean<<<NWIN, 256>>>();
    dim3 gs((TRI + 255) / 256, SIG_NCHUNK);
    k_sigma<<<gs, 256>>>();
    k_chol<<<NWIN, 512, CHOL_SMEM>>>(Y);
    k_final<<<1, 256>>>((float*)d_out);
}